// round 2
// baseline (speedup 1.0000x reference)
#include <cuda_runtime.h>
#include <cuda_bf16.h>

#define NN 100000
#define EE 600000
#define NB_CHUNK 98  // ceil(NN/1024)

// ---- scratch (device globals; allocation is forbidden) ----
__device__ int   g_deg[NN];
__device__ int   g_off[NN];
__device__ int   g_cursor[NN];
__device__ float g_invdeg[NN];
__device__ int   g_csrc[EE];
__device__ int   g_blockSum[NB_CHUNK];
__device__ int   g_chunkBase[NB_CHUNK];
__device__ float g_agg[(size_t)NN * 128];
__device__ float g_h[(size_t)NN * 128];
__device__ int   g_is64;

// Detect whether edge_index is stored as int64 or int32.
// If int32, interpreting the first 32 words as int64 packs two random
// indices per word -> value >= 2^32 with overwhelming probability.
__global__ void k_detect(const void* ei) {
    if (threadIdx.x == 0) {
        const long long* p = (const long long*)ei;
        int ok = 1;
        for (int i = 0; i < 32; i++) {
            long long v = p[i];
            if (v < 0 || v >= NN) ok = 0;
        }
        g_is64 = ok;
    }
}

__device__ __forceinline__ int edge_at(const void* ei, int idx, int is64) {
    return is64 ? (int)((const long long*)ei)[idx] : ((const int*)ei)[idx];
}

__global__ void k_zero() {
    int i = blockIdx.x * blockDim.x + threadIdx.x;
    if (i < NN) g_deg[i] = 0;
}

__global__ void k_count(const void* ei) {
    int is64 = g_is64;
    int e = blockIdx.x * blockDim.x + threadIdx.x;
    if (e < EE) {
        int d = edge_at(ei, EE + e, is64);
        atomicAdd(&g_deg[d], 1);
    }
}

__global__ void k_block_sums() {
    __shared__ int sh[256];
    int b = blockIdx.x, t = threadIdx.x;
    int base = b * 1024;
    int s = 0;
    for (int j = t; j < 1024; j += 256) {
        int i = base + j;
        if (i < NN) s += g_deg[i];
    }
    sh[t] = s;
    __syncthreads();
    for (int o = 128; o > 0; o >>= 1) {
        if (t < o) sh[t] += sh[t + o];
        __syncthreads();
    }
    if (t == 0) g_blockSum[b] = sh[0];
}

__global__ void k_scan_blocks() {
    if (threadIdx.x == 0) {
        int acc = 0;
        for (int b = 0; b < NB_CHUNK; b++) {
            g_chunkBase[b] = acc;
            acc += g_blockSum[b];
        }
    }
}

__global__ void k_chunk_scan() {
    __shared__ int tsum[256];
    __shared__ int tpre[256];
    int b = blockIdx.x, t = threadIdx.x;
    int base = b * 1024;
    int v[4];
    int s = 0;
#pragma unroll
    for (int j = 0; j < 4; j++) {
        int i = base + t * 4 + j;
        v[j] = (i < NN) ? g_deg[i] : 0;
        s += v[j];
    }
    tsum[t] = s;
    __syncthreads();
    if (t == 0) {
        int acc = g_chunkBase[b];
        for (int k = 0; k < 256; k++) {
            tpre[k] = acc;
            acc += tsum[k];
        }
    }
    __syncthreads();
    int acc = tpre[t];
#pragma unroll
    for (int j = 0; j < 4; j++) {
        int i = base + t * 4 + j;
        if (i < NN) {
            g_off[i] = acc;
            g_cursor[i] = acc;
            g_invdeg[i] = 1.0f / fmaxf((float)v[j], 1.0f);
        }
        acc += v[j];
    }
}

__global__ void k_fill(const void* ei) {
    int is64 = g_is64;
    int e = blockIdx.x * blockDim.x + threadIdx.x;
    if (e < EE) {
        int s = edge_at(ei, e, is64);
        int d = edge_at(ei, EE + e, is64);
        int pos = atomicAdd(&g_cursor[d], 1);
        g_csrc[pos] = s;
    }
}

// One warp per node: gather-sum 128-float neighbor features (float4 per lane),
// scale by inv_deg, write mean aggregation.
__global__ void k_aggregate(const float* __restrict__ feat, float* __restrict__ agg) {
    int node = (blockIdx.x * blockDim.x + threadIdx.x) >> 5;
    if (node >= NN) return;
    int lane = threadIdx.x & 31;
    int s = g_off[node], d = g_deg[node];
    float4 acc = make_float4(0.f, 0.f, 0.f, 0.f);
    for (int k = 0; k < d; k++) {
        int j = g_csrc[s + k];
        float4 v = ((const float4*)(feat + (size_t)j * 128))[lane];
        acc.x += v.x; acc.y += v.y; acc.z += v.z; acc.w += v.w;
    }
    float sc = g_invdeg[node];
    acc.x *= sc; acc.y *= sc; acc.z *= sc; acc.w *= sc;
    ((float4*)(agg + (size_t)node * 128))[lane] = acc;
}

// Fused dual-GEMM: out[i] = agg[i] @ Wl + feat[i] @ Wr + bias  (optionally ReLU)
// Treated as M x 256 @ 256 x BN with A = [agg | feat], W = [Wl ; Wr].
template <int BN, bool RELU>
__global__ __launch_bounds__(256) void k_gemm(
    const float* __restrict__ A1, const float* __restrict__ A2,
    const float* __restrict__ Wl, const float* __restrict__ Wr,
    const float* __restrict__ bias, float* __restrict__ out) {
    constexpr int BM = 64, BK = 32;
    constexpr int CPT = BN / 32;  // cols per thread (4 for BN=128, 1 for BN=32)
    constexpr int RPT = 8;        // rows per thread
    __shared__ float As[BK][BM + 1];  // +1 pad -> stride 65, conflict-free
    __shared__ float Ws[BK][BN];

    int t = threadIdx.x;
    int tx = t & 31, ty = t >> 5;
    int rowBase = blockIdx.x * BM;

    float acc[RPT][CPT];
#pragma unroll
    for (int r = 0; r < RPT; r++)
#pragma unroll
        for (int c = 0; c < CPT; c++) acc[r][c] = 0.f;

    for (int kc = 0; kc < 256; kc += BK) {
        const float* Ap = (kc < 128) ? A1 : A2;
        const float* Wp = (kc < 128) ? Wl : Wr;
        int k0 = kc & 127;
        // Load A tile (64 rows x 32 k), transposed into smem
#pragma unroll
        for (int i = 0; i < BM * BK / 256; i++) {
            int idx = t + i * 256;
            int r = idx >> 5;
            int kk = idx & 31;
            int grow = rowBase + r;
            float v = (grow < NN) ? Ap[(size_t)grow * 128 + k0 + kk] : 0.f;
            As[kk][r] = v;
        }
        // Load W tile (32 k x BN)
#pragma unroll
        for (int i = 0; i < BK * BN / 256; i++) {
            int idx = t + i * 256;
            int kk = idx / BN;
            int c = idx % BN;
            Ws[kk][c] = Wp[(size_t)(k0 + kk) * BN + c];
        }
        __syncthreads();
#pragma unroll
        for (int kk = 0; kk < BK; kk++) {
            float a[RPT];
#pragma unroll
            for (int r = 0; r < RPT; r++) a[r] = As[kk][ty * RPT + r];
            float w[CPT];
            if constexpr (CPT == 4) {
                float4 w4 = *(const float4*)&Ws[kk][tx * 4];
                w[0] = w4.x; w[1] = w4.y; w[2] = w4.z; w[3] = w4.w;
            } else {
                w[0] = Ws[kk][tx];
            }
#pragma unroll
            for (int r = 0; r < RPT; r++)
#pragma unroll
                for (int c = 0; c < CPT; c++) acc[r][c] += a[r] * w[c];
        }
        __syncthreads();
    }

#pragma unroll
    for (int r = 0; r < RPT; r++) {
        int grow = rowBase + ty * RPT + r;
        if (grow < NN) {
            if constexpr (CPT == 4) {
                float4 v;
                v.x = acc[r][0] + bias[tx * 4 + 0];
                v.y = acc[r][1] + bias[tx * 4 + 1];
                v.z = acc[r][2] + bias[tx * 4 + 2];
                v.w = acc[r][3] + bias[tx * 4 + 3];
                if (RELU) {
                    v.x = fmaxf(v.x, 0.f); v.y = fmaxf(v.y, 0.f);
                    v.z = fmaxf(v.z, 0.f); v.w = fmaxf(v.w, 0.f);
                }
                *(float4*)&out[(size_t)grow * BN + tx * 4] = v;
            } else {
                float v = acc[r][0] + bias[tx];
                if (RELU) v = fmaxf(v, 0.f);
                out[(size_t)grow * BN + tx] = v;
            }
        }
    }
}

extern "C" void kernel_launch(void* const* d_in, const int* in_sizes, int n_in,
                              void* d_out, int out_size) {
    const float* x   = (const float*)d_in[0];
    const void*  ei  = d_in[1];
    const float* W1l = (const float*)d_in[2];
    const float* b1  = (const float*)d_in[3];
    const float* W1r = (const float*)d_in[4];
    const float* W2l = (const float*)d_in[5];
    const float* b2  = (const float*)d_in[6];
    const float* W2r = (const float*)d_in[7];
    float* out = (float*)d_out;

    float* agg = nullptr;
    float* h = nullptr;
    cudaGetSymbolAddress((void**)&agg, g_agg);
    cudaGetSymbolAddress((void**)&h, g_h);

    // CSR build
    k_detect<<<1, 32>>>(ei);
    k_zero<<<(NN + 255) / 256, 256>>>();
    k_count<<<(EE + 255) / 256, 256>>>(ei);
    k_block_sums<<<NB_CHUNK, 256>>>();
    k_scan_blocks<<<1, 32>>>();
    k_chunk_scan<<<NB_CHUNK, 256>>>();
    k_fill<<<(EE + 255) / 256, 256>>>(ei);

    // Layer 1: agg = mean_nbr(x); h = relu(agg@W1l + x@W1r + b1)
    k_aggregate<<<(NN + 7) / 8, 256>>>(x, agg);
    k_gemm<128, true><<<(NN + 63) / 64, 256>>>(agg, x, W1l, W1r, b1, h);

    // Layer 2: agg2 = mean_nbr(h); out = agg2@W2l + h@W2r + b2
    k_aggregate<<<(NN + 7) / 8, 256>>>(h, agg);
    k_gemm<32, false><<<(NN + 63) / 64, 256>>>(agg, h, W2l, W2r, b2, out);
}

// round 4
// speedup vs baseline: 1.3319x; 1.3319x over previous
#include <cuda_runtime.h>
#include <cuda_bf16.h>

#define NN 100000
#define EE 600000
#define NB_CHUNK 98  // ceil(NN/1024)

// ---- scratch (device globals; allocation is forbidden) ----
__device__ int   g_deg[NN];
__device__ int   g_off[NN];
__device__ int   g_cursor[NN];
__device__ float g_invdeg[NN];
__device__ int   g_csrc[EE];
__device__ int   g_blockSum[NB_CHUNK];
__device__ int   g_chunkBase[NB_CHUNK];
__device__ float g_P[(size_t)NN * 256];  // layer-1 GEMM out: [x@W1l | x@W1r]
__device__ float g_h[(size_t)NN * 128];  // layer-1 activations
__device__ float g_Q[(size_t)NN * 64];   // layer-2 GEMM out: [h@W2l | h@W2r]
__device__ int   g_is64;

// ---------------- edge dtype detect ----------------
__global__ void k_detect(const void* ei) {
    if (threadIdx.x == 0) {
        const long long* p = (const long long*)ei;
        int ok = 1;
        for (int i = 0; i < 32; i++) {
            long long v = p[i];
            if (v < 0 || v >= NN) ok = 0;
        }
        g_is64 = ok;
    }
}

__device__ __forceinline__ int edge_at(const void* ei, int idx, int is64) {
    return is64 ? (int)((const long long*)ei)[idx] : ((const int*)ei)[idx];
}

// ---------------- CSR build ----------------
__global__ void k_zero() {
    int i = blockIdx.x * blockDim.x + threadIdx.x;
    if (i < NN) g_deg[i] = 0;
}

__global__ void k_count(const void* ei) {
    int is64 = g_is64;
    int e = blockIdx.x * blockDim.x + threadIdx.x;
    if (e < EE) {
        int d = edge_at(ei, EE + e, is64);
        atomicAdd(&g_deg[d], 1);
    }
}

__global__ void k_block_sums() {
    __shared__ int sh[256];
    int b = blockIdx.x, t = threadIdx.x;
    int base = b * 1024;
    int s = 0;
    for (int j = t; j < 1024; j += 256) {
        int i = base + j;
        if (i < NN) s += g_deg[i];
    }
    sh[t] = s;
    __syncthreads();
    for (int o = 128; o > 0; o >>= 1) {
        if (t < o) sh[t] += sh[t + o];
        __syncthreads();
    }
    if (t == 0) g_blockSum[b] = sh[0];
}

__global__ void k_scan_blocks() {
    if (threadIdx.x == 0) {
        int acc = 0;
        for (int b = 0; b < NB_CHUNK; b++) {
            g_chunkBase[b] = acc;
            acc += g_blockSum[b];
        }
    }
}

__global__ void k_chunk_scan() {
    __shared__ int tsum[256];
    __shared__ int tpre[256];
    int b = blockIdx.x, t = threadIdx.x;
    int base = b * 1024;
    int v[4];
    int s = 0;
#pragma unroll
    for (int j = 0; j < 4; j++) {
        int i = base + t * 4 + j;
        v[j] = (i < NN) ? g_deg[i] : 0;
        s += v[j];
    }
    tsum[t] = s;
    __syncthreads();
    if (t == 0) {
        int acc = g_chunkBase[b];
        for (int k = 0; k < 256; k++) {
            tpre[k] = acc;
            acc += tsum[k];
        }
    }
    __syncthreads();
    int acc = tpre[t];
#pragma unroll
    for (int j = 0; j < 4; j++) {
        int i = base + t * 4 + j;
        if (i < NN) {
            g_off[i] = acc;
            g_cursor[i] = acc;
            g_invdeg[i] = 1.0f / fmaxf((float)v[j], 1.0f);
        }
        acc += v[j];
    }
}

__global__ void k_fill(const void* ei) {
    int is64 = g_is64;
    int e = blockIdx.x * blockDim.x + threadIdx.x;
    if (e < EE) {
        int s = edge_at(ei, e, is64);
        int d = edge_at(ei, EE + e, is64);
        int pos = atomicAdd(&g_cursor[d], 1);
        g_csrc[pos] = s;
    }
}

// ---------------- tf32 MMA GEMM ----------------
__device__ __forceinline__ unsigned f2tf(float f) {
    unsigned r;
    asm("cvt.rna.tf32.f32 %0, %1;" : "=r"(r) : "f"(f));
    return r;
}

__device__ __forceinline__ void mma8(float* c, const unsigned* a, const unsigned* b) {
    asm volatile(
        "mma.sync.aligned.m16n8k8.row.col.f32.tf32.tf32.f32 "
        "{%0,%1,%2,%3},{%4,%5,%6,%7},{%8,%9},{%0,%1,%2,%3};"
        : "+f"(c[0]), "+f"(c[1]), "+f"(c[2]), "+f"(c[3])
        : "r"(a[0]), "r"(a[1]), "r"(a[2]), "r"(a[3]), "r"(b[0]), "r"(b[1]));
}

// C[M, *] tile = A[M,128] @ B[128,BN]  (tf32 mma, K=128 fixed)
// DUALB=false: grid.y selects B0/B1 (each [128, BN] row-major), colBase = y*BN.
// DUALB=true : B tile is [B0 | B1] side by side, each [128, BN/2] row-major.
template <int BN, int WARPS_N, bool DUALB>
__global__ __launch_bounds__(256) void k_mma(
    const float* __restrict__ A, const float* __restrict__ B0,
    const float* __restrict__ B1, float* __restrict__ C, int ldc) {
    constexpr int WARPS_M = 8 / WARPS_N;
    constexpr int WM = 128 / WARPS_M;
    constexpr int WN = BN / WARPS_N;
    constexpr int MI = WM / 16;
    constexpr int NI = WN / 8;
    constexpr int LDA = 36;       // pad: conflict-free frag loads, 16B-aligned rows
    constexpr int LDB = BN + 8;   // pad: conflict-free frag loads, 16B-aligned rows

    __shared__ unsigned As[128 * LDA];
    __shared__ unsigned Bs[32 * LDB];

    int t = threadIdx.x;
    int lane = t & 31, w = t >> 5;
    int gid = lane >> 2, tid4 = lane & 3;
    int wm = (w / WARPS_N) * WM;
    int wn = (w % WARPS_N) * WN;
    int rowBase = blockIdx.x * 128;
    int colBase = DUALB ? 0 : blockIdx.y * BN;
    const float* B = DUALB ? B0 : (blockIdx.y ? B1 : B0);

    float acc[MI][NI][4];
#pragma unroll
    for (int mi = 0; mi < MI; mi++)
#pragma unroll
        for (int ni = 0; ni < NI; ni++)
#pragma unroll
            for (int j = 0; j < 4; j++) acc[mi][ni][j] = 0.f;

    for (int k0 = 0; k0 < 128; k0 += 32) {
        // A tile: 128 rows x 32 k  (1024 float4 slots)
#pragma unroll
        for (int i = 0; i < 4; i++) {
            int idx = t + i * 256;
            int r = idx >> 3, seg = idx & 7;
            int grow = rowBase + r;
            float4 v = make_float4(0.f, 0.f, 0.f, 0.f);
            if (grow < NN) v = *(const float4*)&A[(size_t)grow * 128 + k0 + seg * 4];
            uint4 u;
            u.x = f2tf(v.x); u.y = f2tf(v.y); u.z = f2tf(v.z); u.w = f2tf(v.w);
            *(uint4*)&As[r * LDA + seg * 4] = u;
        }
        // B tile: 32 k x BN
        if (DUALB) {
            constexpr int HALF = BN / 2;
#pragma unroll
            for (int i = 0; i < BN * 32 / 1024; i++) {
                int idx = t + i * 256;
                int kk = idx / (BN / 4);
                int n = (idx % (BN / 4)) * 4;
                const float* src = (n < HALF) ? &B0[(size_t)(k0 + kk) * HALF + n]
                                              : &B1[(size_t)(k0 + kk) * HALF + n - HALF];
                float4 v = *(const float4*)src;
                uint4 u;
                u.x = f2tf(v.x); u.y = f2tf(v.y); u.z = f2tf(v.z); u.w = f2tf(v.w);
                *(uint4*)&Bs[kk * LDB + n] = u;
            }
        } else {
#pragma unroll
            for (int i = 0; i < BN * 32 / 1024; i++) {
                int idx = t + i * 256;
                int kk = idx / (BN / 4);
                int n = (idx % (BN / 4)) * 4;
                float4 v = *(const float4*)&B[(size_t)(k0 + kk) * BN + n];
                uint4 u;
                u.x = f2tf(v.x); u.y = f2tf(v.y); u.z = f2tf(v.z); u.w = f2tf(v.w);
                *(uint4*)&Bs[kk * LDB + n] = u;
            }
        }
        __syncthreads();

#pragma unroll
        for (int ks = 0; ks < 32; ks += 8) {
            unsigned a[MI][4], b[NI][2];
#pragma unroll
            for (int mi = 0; mi < MI; mi++) {
                int r = wm + mi * 16 + gid;
                a[mi][0] = As[r * LDA + ks + tid4];
                a[mi][1] = As[(r + 8) * LDA + ks + tid4];
                a[mi][2] = As[r * LDA + ks + tid4 + 4];
                a[mi][3] = As[(r + 8) * LDA + ks + tid4 + 4];
            }
#pragma unroll
            for (int ni = 0; ni < NI; ni++) {
                int c = wn + ni * 8 + gid;
                b[ni][0] = Bs[(ks + tid4) * LDB + c];
                b[ni][1] = Bs[(ks + tid4 + 4) * LDB + c];
            }
#pragma unroll
            for (int mi = 0; mi < MI; mi++)
#pragma unroll
                for (int ni = 0; ni < NI; ni++) mma8(acc[mi][ni], a[mi], b[ni]);
        }
        __syncthreads();
    }

    // epilogue
#pragma unroll
    for (int mi = 0; mi < MI; mi++) {
#pragma unroll
        for (int ni = 0; ni < NI; ni++) {
            int r0 = rowBase + wm + mi * 16 + gid;
            int c = colBase + wn + ni * 8 + 2 * tid4;
            if (r0 < NN) {
                float2 v = make_float2(acc[mi][ni][0], acc[mi][ni][1]);
                *(float2*)&C[(size_t)r0 * ldc + c] = v;
            }
            if (r0 + 8 < NN) {
                float2 v = make_float2(acc[mi][ni][2], acc[mi][ni][3]);
                *(float2*)&C[(size_t)(r0 + 8) * ldc + c] = v;
            }
        }
    }
}

// ---------------- post-GEMM aggregations ----------------
// h = relu(invdeg * sum_nbr P[:, 0:128] + b1 + P[:, 128:256]); P stride 256
__global__ void k_agg1(const float* __restrict__ P, const float* __restrict__ b1,
                       float* __restrict__ h) {
    int node = (blockIdx.x * blockDim.x + threadIdx.x) >> 5;
    if (node >= NN) return;
    int lane = threadIdx.x & 31;
    int s = g_off[node], d = g_deg[node];
    const float4* P4 = (const float4*)P;  // row stride = 64 float4
    float4 acc = make_float4(0.f, 0.f, 0.f, 0.f);
    int k = 0;
    for (; k + 1 < d; k += 2) {
        int j0 = g_csrc[s + k], j1 = g_csrc[s + k + 1];
        float4 v0 = P4[(size_t)j0 * 64 + lane];
        float4 v1 = P4[(size_t)j1 * 64 + lane];
        acc.x += v0.x + v1.x; acc.y += v0.y + v1.y;
        acc.z += v0.z + v1.z; acc.w += v0.w + v1.w;
    }
    if (k < d) {
        int j = g_csrc[s + k];
        float4 v = P4[(size_t)j * 64 + lane];
        acc.x += v.x; acc.y += v.y; acc.z += v.z; acc.w += v.w;
    }
    float sc = g_invdeg[node];
    float4 r = P4[(size_t)node * 64 + 32 + lane];
    float4 bb = ((const float4*)b1)[lane];
    float4 o;
    o.x = fmaxf(acc.x * sc + bb.x + r.x, 0.f);
    o.y = fmaxf(acc.y * sc + bb.y + r.y, 0.f);
    o.z = fmaxf(acc.z * sc + bb.z + r.z, 0.f);
    o.w = fmaxf(acc.w * sc + bb.w + r.w, 0.f);
    ((float4*)h)[(size_t)node * 32 + lane] = o;
}

// out = invdeg * sum_nbr Q[:, 0:32] + b2 + Q[:, 32:64]; Q stride 64
__global__ void k_agg2(const float* __restrict__ Q, const float* __restrict__ b2,
                       float* __restrict__ out) {
    int node = (blockIdx.x * blockDim.x + threadIdx.x) >> 5;
    if (node >= NN) return;
    int lane = threadIdx.x & 31;
    int s = g_off[node], d = g_deg[node];
    float acc = 0.f;
    int k = 0;
    for (; k + 1 < d; k += 2) {
        int j0 = g_csrc[s + k], j1 = g_csrc[s + k + 1];
        acc += Q[(size_t)j0 * 64 + lane] + Q[(size_t)j1 * 64 + lane];
    }
    if (k < d) acc += Q[(size_t)g_csrc[s + k] * 64 + lane];
    out[(size_t)node * 32 + lane] =
        acc * g_invdeg[node] + b2[lane] + Q[(size_t)node * 64 + 32 + lane];
}

extern "C" void kernel_launch(void* const* d_in, const int* in_sizes, int n_in,
                              void* d_out, int out_size) {
    const float* x   = (const float*)d_in[0];
    const void*  ei  = d_in[1];
    const float* W1l = (const float*)d_in[2];
    const float* b1  = (const float*)d_in[3];
    const float* W1r = (const float*)d_in[4];
    const float* W2l = (const float*)d_in[5];
    const float* b2  = (const float*)d_in[6];
    const float* W2r = (const float*)d_in[7];
    float* out = (float*)d_out;

    float *P = nullptr, *h = nullptr, *Q = nullptr;
    cudaGetSymbolAddress((void**)&P, g_P);
    cudaGetSymbolAddress((void**)&h, g_h);
    cudaGetSymbolAddress((void**)&Q, g_Q);

    // CSR build
    k_detect<<<1, 32>>>(ei);
    k_zero<<<(NN + 255) / 256, 256>>>();
    k_count<<<(EE + 255) / 256, 256>>>(ei);
    k_block_sums<<<NB_CHUNK, 256>>>();
    k_scan_blocks<<<1, 32>>>();
    k_chunk_scan<<<NB_CHUNK, 256>>>();
    k_fill<<<(EE + 255) / 256, 256>>>(ei);

    const int MBLK = (NN + 127) / 128;  // 782

    // Layer 1: P = x @ [W1l | W1r]; h = relu(invdeg*agg(P_l) + b1 + P_r)
    k_mma<128, 4, false><<<dim3(MBLK, 2), 256>>>(x, W1l, W1r, P, 256);
    k_agg1<<<(NN + 7) / 8, 256>>>(P, b1, h);

    // Layer 2: Q = h @ [W2l | W2r]; out = invdeg*agg(Q_l) + b2 + Q_r
    k_mma<64, 2, true><<<dim3(MBLK, 1), 256>>>(h, W2l, W2r, Q, 64);
    k_agg2<<<(NN + 7) / 8, 256>>>(Q, b2, out);
}

// round 6
// speedup vs baseline: 1.8229x; 1.3687x over previous
#include <cuda_runtime.h>
#include <cuda_bf16.h>

#define NN 100000
#define EE 600000
#define NB_CHUNK 98  // ceil(NN/1024)

// ---- scratch (device globals; allocation is forbidden) ----
__device__ int   g_deg[NN];
__device__ int   g_off[NN];
__device__ int   g_cursor[NN];
__device__ float g_invdeg[NN];
__device__ int   g_csrc[EE];
__device__ volatile int g_blkTotal[NB_CHUNK];
__device__ volatile int g_blkFlag[NB_CHUNK];
__device__ float g_P[(size_t)NN * 256];  // layer-1 GEMM out: [x@W1l | x@W1r]
__device__ float g_h[(size_t)NN * 128];  // layer-1 activations
__device__ float g_Q[(size_t)NN * 64];   // layer-2 GEMM out: [h@W2l | h@W2r]
__device__ int   g_is64;

__device__ __forceinline__ int edge_at(const void* ei, int idx, int is64) {
    return is64 ? (int)((const long long*)ei)[idx] : ((const int*)ei)[idx];
}

// ---------------- init: zero degrees, reset scan flags, detect edge dtype ----
__global__ void k_init(const void* ei) {
    int i = blockIdx.x * blockDim.x + threadIdx.x;
    if (i < NN) g_deg[i] = 0;
    if (i < NB_CHUNK) g_blkFlag[i] = 0;
    if (i == 0) {
        const long long* p = (const long long*)ei;
        int ok = 1;
        for (int k = 0; k < 32; k++) {
            long long v = p[k];
            if (v < 0 || v >= NN) ok = 0;
        }
        g_is64 = ok;
    }
}

__global__ void k_count(const void* ei) {
    int is64 = g_is64;
    int e = blockIdx.x * blockDim.x + threadIdx.x;
    if (e < EE) {
        int d = edge_at(ei, EE + e, is64);
        atomicAdd(&g_deg[d], 1);
    }
}

// Single-kernel exclusive scan of g_deg with parallel decoupled lookback.
// 98 blocks (all co-resident on 148 SMs), 1024 nodes per block.
__global__ __launch_bounds__(256) void k_scan() {
    __shared__ int tsum[256];
    __shared__ int tpre[256];
    __shared__ int red[256];
    __shared__ int sh_prefix;
    int b = blockIdx.x, t = threadIdx.x;
    int base = b * 1024;
    int v[4];
    int s = 0;
#pragma unroll
    for (int j = 0; j < 4; j++) {
        int i = base + t * 4 + j;
        v[j] = (i < NN) ? g_deg[i] : 0;
        s += v[j];
    }
    tsum[t] = s;
    __syncthreads();
    if (t == 0) {
        int acc = 0;
        for (int k = 0; k < 256; k++) {
            tpre[k] = acc;
            acc += tsum[k];
        }
        g_blkTotal[b] = acc;
        __threadfence();
        g_blkFlag[b] = 1;
    }
    // parallel lookback: thread t (< b) grabs predecessor t's total
    int mine = 0;
    if (t < b) {
        while (g_blkFlag[t] == 0) {}
        mine = g_blkTotal[t];
    }
    red[t] = mine;
    __syncthreads();
    for (int o = 128; o > 0; o >>= 1) {
        if (t < o) red[t] += red[t + o];
        __syncthreads();
    }
    if (t == 0) sh_prefix = red[0];
    __syncthreads();
    int acc = sh_prefix + tpre[t];
#pragma unroll
    for (int j = 0; j < 4; j++) {
        int i = base + t * 4 + j;
        if (i < NN) {
            g_off[i] = acc;
            g_cursor[i] = acc;
            g_invdeg[i] = 1.0f / fmaxf((float)v[j], 1.0f);
        }
        acc += v[j];
    }
}

__global__ void k_fill(const void* ei) {
    int is64 = g_is64;
    int e = blockIdx.x * blockDim.x + threadIdx.x;
    if (e < EE) {
        int s = edge_at(ei, e, is64);
        int d = edge_at(ei, EE + e, is64);
        int pos = atomicAdd(&g_cursor[d], 1);
        g_csrc[pos] = s;
    }
}

// ---------------- tf32 MMA GEMM (double-buffered) ----------------
__device__ __forceinline__ unsigned f2tf(float f) {
    unsigned r;
    asm("cvt.rna.tf32.f32 %0, %1;" : "=r"(r) : "f"(f));
    return r;
}

__device__ __forceinline__ void mma8(float* c, const unsigned* a, const unsigned* b) {
    asm volatile(
        "mma.sync.aligned.m16n8k8.row.col.f32.tf32.tf32.f32 "
        "{%0,%1,%2,%3},{%4,%5,%6,%7},{%8,%9},{%0,%1,%2,%3};"
        : "+f"(c[0]), "+f"(c[1]), "+f"(c[2]), "+f"(c[3])
        : "r"(a[0]), "r"(a[1]), "r"(a[2]), "r"(a[3]), "r"(b[0]), "r"(b[1]));
}

// C[M, *] tile = A[M,128] @ B[128,BN]  (tf32 mma, K=128 fixed)
// DUALB=false: grid.y selects B0/B1 (each [128, BN] row-major), colBase = y*BN.
// DUALB=true : B tile is [B0 | B1] side by side, each [128, BN/2] row-major.
template <int BN, int WARPS_N, bool DUALB>
__global__ __launch_bounds__(256) void k_mma(
    const float* __restrict__ A, const float* __restrict__ B0,
    const float* __restrict__ B1, float* __restrict__ C, int ldc) {
    constexpr int WARPS_M = 8 / WARPS_N;
    constexpr int WM = 128 / WARPS_M;
    constexpr int WN = BN / WARPS_N;
    constexpr int MI = WM / 16;
    constexpr int NI = WN / 8;
    constexpr int LDA = 36;      // pad: conflict-free frag loads, 16B-aligned rows
    constexpr int LDB = BN + 8;  // pad: conflict-free frag loads, 16B-aligned rows
    constexpr int ASZ = 128 * LDA;
    constexpr int BSZ = 32 * LDB;
    constexpr int BLD = BN * 32 / 1024;  // B float4 slots per thread

    extern __shared__ unsigned sh[];
    unsigned* As = sh;             // 2 * ASZ
    unsigned* Bs = sh + 2 * ASZ;   // 2 * BSZ

    int t = threadIdx.x;
    int lane = t & 31, w = t >> 5;
    int gid = lane >> 2, tid4 = lane & 3;
    int wm = (w / WARPS_N) * WM;
    int wn = (w % WARPS_N) * WN;
    int rowBase = blockIdx.x * 128;
    int colBase = DUALB ? 0 : blockIdx.y * BN;
    const float* B = DUALB ? B0 : (blockIdx.y ? B1 : B0);

    float4 aR[4];
    float4 bR[BLD];

    auto ldTiles = [&](int k0) {
#pragma unroll
        for (int i = 0; i < 4; i++) {
            int idx = t + i * 256;
            int r = idx >> 3, seg = idx & 7;
            int grow = rowBase + r;
            aR[i] = (grow < NN) ? *(const float4*)&A[(size_t)grow * 128 + k0 + seg * 4]
                                : make_float4(0.f, 0.f, 0.f, 0.f);
        }
        if (DUALB) {
            constexpr int HALF = BN / 2;
#pragma unroll
            for (int i = 0; i < BLD; i++) {
                int idx = t + i * 256;
                int kk = idx / (BN / 4);
                int n = (idx % (BN / 4)) * 4;
                const float* src = (n < HALF) ? &B0[(size_t)(k0 + kk) * HALF + n]
                                              : &B1[(size_t)(k0 + kk) * HALF + n - HALF];
                bR[i] = *(const float4*)src;
            }
        } else {
#pragma unroll
            for (int i = 0; i < BLD; i++) {
                int idx = t + i * 256;
                int kk = idx / (BN / 4);
                int n = (idx % (BN / 4)) * 4;
                bR[i] = *(const float4*)&B[(size_t)(k0 + kk) * BN + n];
            }
        }
    };

    auto stTiles = [&](int buf) {
        unsigned* Ab = As + buf * ASZ;
        unsigned* Bb = Bs + buf * BSZ;
#pragma unroll
        for (int i = 0; i < 4; i++) {
            int idx = t + i * 256;
            int r = idx >> 3, seg = idx & 7;
            uint4 u;
            u.x = f2tf(aR[i].x); u.y = f2tf(aR[i].y);
            u.z = f2tf(aR[i].z); u.w = f2tf(aR[i].w);
            *(uint4*)&Ab[r * LDA + seg * 4] = u;
        }
#pragma unroll
        for (int i = 0; i < BLD; i++) {
            int idx = t + i * 256;
            int kk = idx / (BN / 4);
            int n = (idx % (BN / 4)) * 4;
            uint4 u;
            u.x = f2tf(bR[i].x); u.y = f2tf(bR[i].y);
            u.z = f2tf(bR[i].z); u.w = f2tf(bR[i].w);
            *(uint4*)&Bb[kk * LDB + n] = u;
        }
    };

    float acc[MI][NI][4];
#pragma unroll
    for (int mi = 0; mi < MI; mi++)
#pragma unroll
        for (int ni = 0; ni < NI; ni++)
#pragma unroll
            for (int j = 0; j < 4; j++) acc[mi][ni][j] = 0.f;

    ldTiles(0);
    stTiles(0);
    __syncthreads();

#pragma unroll
    for (int k0 = 0; k0 < 128; k0 += 32) {
        int cur = (k0 >> 5) & 1;
        if (k0 < 96) ldTiles(k0 + 32);  // overlap next-tile loads with compute
        const unsigned* Ab = As + cur * ASZ;
        const unsigned* Bb = Bs + cur * BSZ;
#pragma unroll
        for (int ks = 0; ks < 32; ks += 8) {
            unsigned a[MI][4], b[NI][2];
#pragma unroll
            for (int mi = 0; mi < MI; mi++) {
                int r = wm + mi * 16 + gid;
                a[mi][0] = Ab[r * LDA + ks + tid4];
                a[mi][1] = Ab[(r + 8) * LDA + ks + tid4];
                a[mi][2] = Ab[r * LDA + ks + tid4 + 4];
                a[mi][3] = Ab[(r + 8) * LDA + ks + tid4 + 4];
            }
#pragma unroll
            for (int ni = 0; ni < NI; ni++) {
                int c = wn + ni * 8 + gid;
                b[ni][0] = Bb[(ks + tid4) * LDB + c];
                b[ni][1] = Bb[(ks + tid4 + 4) * LDB + c];
            }
#pragma unroll
            for (int mi = 0; mi < MI; mi++)
#pragma unroll
                for (int ni = 0; ni < NI; ni++) mma8(acc[mi][ni], a[mi], b[ni]);
        }
        if (k0 < 96) {
            __syncthreads();
            stTiles(cur ^ 1);
            __syncthreads();
        }
    }

    // epilogue
#pragma unroll
    for (int mi = 0; mi < MI; mi++) {
#pragma unroll
        for (int ni = 0; ni < NI; ni++) {
            int r0 = rowBase + wm + mi * 16 + gid;
            int c = colBase + wn + ni * 8 + 2 * tid4;
            if (r0 < NN) {
                float2 v = make_float2(acc[mi][ni][0], acc[mi][ni][1]);
                *(float2*)&C[(size_t)r0 * ldc + c] = v;
            }
            if (r0 + 8 < NN) {
                float2 v = make_float2(acc[mi][ni][2], acc[mi][ni][3]);
                *(float2*)&C[(size_t)(r0 + 8) * ldc + c] = v;
            }
        }
    }
}

// ---------------- post-GEMM aggregations ----------------
// h = relu(invdeg * sum_nbr P[:, 0:128] + b1 + P[:, 128:256]); P stride 256
__global__ void k_agg1(const float* __restrict__ P, const float* __restrict__ b1,
                       float* __restrict__ h) {
    int node = (blockIdx.x * blockDim.x + threadIdx.x) >> 5;
    if (node >= NN) return;
    int lane = threadIdx.x & 31;
    int s = g_off[node], d = g_deg[node];
    const float4* P4 = (const float4*)P;  // row stride = 64 float4
    float4 acc = make_float4(0.f, 0.f, 0.f, 0.f);
    int k = 0;
    for (; k + 1 < d; k += 2) {
        int j0 = g_csrc[s + k], j1 = g_csrc[s + k + 1];
        float4 v0 = P4[(size_t)j0 * 64 + lane];
        float4 v1 = P4[(size_t)j1 * 64 + lane];
        acc.x += v0.x + v1.x; acc.y += v0.y + v1.y;
        acc.z += v0.z + v1.z; acc.w += v0.w + v1.w;
    }
    if (k < d) {
        int j = g_csrc[s + k];
        float4 v = P4[(size_t)j * 64 + lane];
        acc.x += v.x; acc.y += v.y; acc.z += v.z; acc.w += v.w;
    }
    float sc = g_invdeg[node];
    float4 r = P4[(size_t)node * 64 + 32 + lane];
    float4 bb = ((const float4*)b1)[lane];
    float4 o;
    o.x = fmaxf(acc.x * sc + bb.x + r.x, 0.f);
    o.y = fmaxf(acc.y * sc + bb.y + r.y, 0.f);
    o.z = fmaxf(acc.z * sc + bb.z + r.z, 0.f);
    o.w = fmaxf(acc.w * sc + bb.w + r.w, 0.f);
    ((float4*)h)[(size_t)node * 32 + lane] = o;
}

// out = invdeg * sum_nbr Q[:, 0:32] + b2 + Q[:, 32:64]; Q stride 64
__global__ void k_agg2(const float* __restrict__ Q, const float* __restrict__ b2,
                       float* __restrict__ out) {
    int node = (blockIdx.x * blockDim.x + threadIdx.x) >> 5;
    if (node >= NN) return;
    int lane = threadIdx.x & 31;
    int s = g_off[node], d = g_deg[node];
    float acc = 0.f;
    int k = 0;
    for (; k + 1 < d; k += 2) {
        int j0 = g_csrc[s + k], j1 = g_csrc[s + k + 1];
        acc += Q[(size_t)j0 * 64 + lane] + Q[(size_t)j1 * 64 + lane];
    }
    if (k < d) acc += Q[(size_t)g_csrc[s + k] * 64 + lane];
    out[(size_t)node * 32 + lane] =
        acc * g_invdeg[node] + b2[lane] + Q[(size_t)node * 64 + 32 + lane];
}

extern "C" void kernel_launch(void* const* d_in, const int* in_sizes, int n_in,
                              void* d_out, int out_size) {
    const float* x   = (const float*)d_in[0];
    const void*  ei  = d_in[1];
    const float* W1l = (const float*)d_in[2];
    const float* b1  = (const float*)d_in[3];
    const float* W1r = (const float*)d_in[4];
    const float* W2l = (const float*)d_in[5];
    const float* b2  = (const float*)d_in[6];
    const float* W2r = (const float*)d_in[7];
    float* out = (float*)d_out;

    float *P = nullptr, *h = nullptr, *Q = nullptr;
    cudaGetSymbolAddress((void**)&P, g_P);
    cudaGetSymbolAddress((void**)&h, g_h);
    cudaGetSymbolAddress((void**)&Q, g_Q);

    // dynamic smem: double-buffered As + Bs
    const int smem1 = 2 * (128 * 36 + 32 * (128 + 8)) * (int)sizeof(unsigned);  // 71680
    const int smem2 = 2 * (128 * 36 + 32 * (64 + 8)) * (int)sizeof(unsigned);   // 55296
    cudaFuncSetAttribute(k_mma<128, 4, false>,
                         cudaFuncAttributeMaxDynamicSharedMemorySize, smem1);
    cudaFuncSetAttribute(k_mma<64, 2, true>,
                         cudaFuncAttributeMaxDynamicSharedMemorySize, smem2);

    // CSR build (4 launches)
    k_init<<<(NN + 255) / 256, 256>>>(ei);
    k_count<<<(EE + 255) / 256, 256>>>(ei);
    k_scan<<<NB_CHUNK, 256>>>();
    k_fill<<<(EE + 255) / 256, 256>>>(ei);

    const int MBLK = (NN + 127) / 128;  // 782

    // Layer 1: P = x @ [W1l | W1r]; h = relu(invdeg*agg(P_l) + b1 + P_r)
    k_mma<128, 4, false><<<dim3(MBLK, 2), 256, smem1>>>(x, W1l, W1r, P, 256);
    k_agg1<<<(NN + 7) / 8, 256>>>(P, b1, h);

    // Layer 2: Q = h @ [W2l | W2r]; out = invdeg*agg(Q_l) + b2 + Q_r
    k_mma<64, 2, true><<<dim3(MBLK, 1), 256, smem2>>>(h, W2l, W2r, Q, 64);
    k_agg2<<<(NN + 7) / 8, 256>>>(Q, b2, out);
}

// round 7
// speedup vs baseline: 1.9851x; 1.0890x over previous
#include <cuda_runtime.h>
#include <cuda_bf16.h>

#define NN 100000
#define EE 600000
#define NB_CHUNK 98  // ceil(NN/1024)

// ---- scratch (device globals; allocation is forbidden) ----
__device__ int   g_deg[NN];
__device__ int   g_off[NN];
__device__ int   g_cursor[NN];
__device__ float g_invdeg[NN];
__device__ int   g_csrc[EE];
__device__ volatile int g_blkTotal[NB_CHUNK];
__device__ volatile int g_blkFlag[NB_CHUNK];
__device__ float g_agg[(size_t)NN * 128];  // mean_nbr(x)
__device__ float g_h[(size_t)NN * 128];    // layer-1 activations
__device__ float g_Q[(size_t)NN * 64];     // layer-2 GEMM out: [h@W2l | h@W2r]
__device__ int   g_is64;

// ---------------- init: zero degrees, reset scan flags, detect edge dtype ----
__global__ void k_init(const void* ei) {
    int i = blockIdx.x * blockDim.x + threadIdx.x;
    if (i < NN) g_deg[i] = 0;
    if (i < NB_CHUNK) g_blkFlag[i] = 0;
    if (i == 0) {
        const long long* p = (const long long*)ei;
        int ok = 1;
        for (int k = 0; k < 32; k++) {
            long long v = p[k];
            if (v < 0 || v >= NN) ok = 0;
        }
        g_is64 = ok;
    }
}

// 2 edges per thread, vectorized loads of the dst half
__global__ void k_count(const void* ei) {
    int e = blockIdx.x * blockDim.x + threadIdx.x;
    if (e >= EE / 2) return;
    int d0, d1;
    if (g_is64) {
        longlong2 v = ((const longlong2*)ei)[EE / 2 + e];
        d0 = (int)v.x; d1 = (int)v.y;
    } else {
        int2 v = ((const int2*)ei)[EE / 2 + e];
        d0 = v.x; d1 = v.y;
    }
    atomicAdd(&g_deg[d0], 1);
    atomicAdd(&g_deg[d1], 1);
}

// Single-kernel exclusive scan of g_deg with parallel decoupled lookback.
__global__ __launch_bounds__(256) void k_scan() {
    __shared__ int tsum[256];
    __shared__ int tpre[256];
    __shared__ int red[256];
    __shared__ int sh_prefix;
    int b = blockIdx.x, t = threadIdx.x;
    int base = b * 1024;
    int v[4];
    int s = 0;
#pragma unroll
    for (int j = 0; j < 4; j++) {
        int i = base + t * 4 + j;
        v[j] = (i < NN) ? g_deg[i] : 0;
        s += v[j];
    }
    tsum[t] = s;
    __syncthreads();
    if (t == 0) {
        int acc = 0;
        for (int k = 0; k < 256; k++) {
            tpre[k] = acc;
            acc += tsum[k];
        }
        g_blkTotal[b] = acc;
        __threadfence();
        g_blkFlag[b] = 1;
    }
    int mine = 0;
    if (t < b) {
        while (g_blkFlag[t] == 0) {}
        mine = g_blkTotal[t];
    }
    red[t] = mine;
    __syncthreads();
    for (int o = 128; o > 0; o >>= 1) {
        if (t < o) red[t] += red[t + o];
        __syncthreads();
    }
    if (t == 0) sh_prefix = red[0];
    __syncthreads();
    int acc = sh_prefix + tpre[t];
#pragma unroll
    for (int j = 0; j < 4; j++) {
        int i = base + t * 4 + j;
        if (i < NN) {
            g_off[i] = acc;
            g_cursor[i] = acc;
            g_invdeg[i] = 1.0f / fmaxf((float)v[j], 1.0f);
        }
        acc += v[j];
    }
}

// 2 edges per thread, vectorized loads of src and dst halves
__global__ void k_fill(const void* ei) {
    int e = blockIdx.x * blockDim.x + threadIdx.x;
    if (e >= EE / 2) return;
    int s0, s1, d0, d1;
    if (g_is64) {
        longlong2 sv = ((const longlong2*)ei)[e];
        longlong2 dv = ((const longlong2*)ei)[EE / 2 + e];
        s0 = (int)sv.x; s1 = (int)sv.y; d0 = (int)dv.x; d1 = (int)dv.y;
    } else {
        int2 sv = ((const int2*)ei)[e];
        int2 dv = ((const int2*)ei)[EE / 2 + e];
        s0 = sv.x; s1 = sv.y; d0 = dv.x; d1 = dv.y;
    }
    g_csrc[atomicAdd(&g_cursor[d0], 1)] = s0;
    g_csrc[atomicAdd(&g_cursor[d1], 1)] = s1;
}

// ---------------- tf32 MMA GEMM (double-buffered) ----------------
__device__ __forceinline__ unsigned f2tf(float f) {
    unsigned r;
    asm("cvt.rna.tf32.f32 %0, %1;" : "=r"(r) : "f"(f));
    return r;
}

__device__ __forceinline__ void mma8(float* c, const unsigned* a, const unsigned* b) {
    asm volatile(
        "mma.sync.aligned.m16n8k8.row.col.f32.tf32.tf32.f32 "
        "{%0,%1,%2,%3},{%4,%5,%6,%7},{%8,%9},{%0,%1,%2,%3};"
        : "+f"(c[0]), "+f"(c[1]), "+f"(c[2]), "+f"(c[3])
        : "r"(a[0]), "r"(a[1]), "r"(a[2]), "r"(a[3]), "r"(b[0]), "r"(b[1]));
}

// C[128-tile, BN] = A[*, KTOT] @ B[KTOT, BN]
// SPLITK: A = [A1 | A2] along K (each 128 wide, row stride 128); B rows 0:128
//         from B0, 128:256 from B1 (each row-major [128, BN]).
// DUALB (!SPLITK): B tile is [B0 | B1] side by side, each [128, BN/2].
// RELU: epilogue adds bias and applies ReLU.
template <int BN, int WARPS_N, int KTOT, bool SPLITK, bool RELU>
__global__ __launch_bounds__(256) void k_mma(
    const float* __restrict__ A1, const float* __restrict__ A2,
    const float* __restrict__ B0, const float* __restrict__ B1,
    const float* __restrict__ bias, float* __restrict__ C, int ldc) {
    constexpr int WARPS_M = 8 / WARPS_N;
    constexpr int WM = 128 / WARPS_M;
    constexpr int WN = BN / WARPS_N;
    constexpr int MI = WM / 16;
    constexpr int NI = WN / 8;
    constexpr int LDA = 36;      // pad: conflict-free frag loads, 16B-aligned rows
    constexpr int LDB = BN + 8;  // pad: conflict-free frag loads, 16B-aligned rows
    constexpr int ASZ = 128 * LDA;
    constexpr int BSZ = 32 * LDB;
    constexpr int BLD = BN * 32 / 1024;  // B float4 slots per thread

    extern __shared__ unsigned sh[];
    unsigned* As = sh;            // 2 * ASZ
    unsigned* Bs = sh + 2 * ASZ;  // 2 * BSZ

    int t = threadIdx.x;
    int lane = t & 31, w = t >> 5;
    int gid = lane >> 2, tid4 = lane & 3;
    int wm = (w / WARPS_N) * WM;
    int wn = (w % WARPS_N) * WN;
    int rowBase = blockIdx.x * 128;

    float4 aR[4];
    float4 bR[BLD];

    auto ldTiles = [&](int k0) {
        const float* Ap = SPLITK ? (k0 < 128 ? A1 : A2) : A1;
        int ka = k0 & 127;
#pragma unroll
        for (int i = 0; i < 4; i++) {
            int idx = t + i * 256;
            int r = idx >> 3, seg = idx & 7;
            int grow = rowBase + r;
            aR[i] = (grow < NN) ? *(const float4*)&Ap[(size_t)grow * 128 + ka + seg * 4]
                                : make_float4(0.f, 0.f, 0.f, 0.f);
        }
        if (SPLITK) {
            const float* Wp = (k0 < 128) ? B0 : B1;
#pragma unroll
            for (int i = 0; i < BLD; i++) {
                int idx = t + i * 256;
                int kk = idx / (BN / 4);
                int n = (idx % (BN / 4)) * 4;
                bR[i] = *(const float4*)&Wp[(size_t)(ka + kk) * BN + n];
            }
        } else {
            constexpr int HALF = BN / 2;
#pragma unroll
            for (int i = 0; i < BLD; i++) {
                int idx = t + i * 256;
                int kk = idx / (BN / 4);
                int n = (idx % (BN / 4)) * 4;
                const float* src = (n < HALF) ? &B0[(size_t)(k0 + kk) * HALF + n]
                                              : &B1[(size_t)(k0 + kk) * HALF + n - HALF];
                bR[i] = *(const float4*)src;
            }
        }
    };

    auto stTiles = [&](int buf) {
        unsigned* Ab = As + buf * ASZ;
        unsigned* Bb = Bs + buf * BSZ;
#pragma unroll
        for (int i = 0; i < 4; i++) {
            int idx = t + i * 256;
            int r = idx >> 3, seg = idx & 7;
            uint4 u;
            u.x = f2tf(aR[i].x); u.y = f2tf(aR[i].y);
            u.z = f2tf(aR[i].z); u.w = f2tf(aR[i].w);
            *(uint4*)&Ab[r * LDA + seg * 4] = u;
        }
#pragma unroll
        for (int i = 0; i < BLD; i++) {
            int idx = t + i * 256;
            int kk = idx / (BN / 4);
            int n = (idx % (BN / 4)) * 4;
            uint4 u;
            u.x = f2tf(bR[i].x); u.y = f2tf(bR[i].y);
            u.z = f2tf(bR[i].z); u.w = f2tf(bR[i].w);
            *(uint4*)&Bb[kk * LDB + n] = u;
        }
    };

    float acc[MI][NI][4];
#pragma unroll
    for (int mi = 0; mi < MI; mi++)
#pragma unroll
        for (int ni = 0; ni < NI; ni++)
#pragma unroll
            for (int j = 0; j < 4; j++) acc[mi][ni][j] = 0.f;

    ldTiles(0);
    stTiles(0);
    __syncthreads();

#pragma unroll
    for (int k0 = 0; k0 < KTOT; k0 += 32) {
        int cur = (k0 >> 5) & 1;
        if (k0 + 32 < KTOT) ldTiles(k0 + 32);  // overlap next-tile loads
        const unsigned* Ab = As + cur * ASZ;
        const unsigned* Bb = Bs + cur * BSZ;
#pragma unroll
        for (int ks = 0; ks < 32; ks += 8) {
            unsigned a[MI][4], b[NI][2];
#pragma unroll
            for (int mi = 0; mi < MI; mi++) {
                int r = wm + mi * 16 + gid;
                a[mi][0] = Ab[r * LDA + ks + tid4];
                a[mi][1] = Ab[(r + 8) * LDA + ks + tid4];
                a[mi][2] = Ab[r * LDA + ks + tid4 + 4];
                a[mi][3] = Ab[(r + 8) * LDA + ks + tid4 + 4];
            }
#pragma unroll
            for (int ni = 0; ni < NI; ni++) {
                int c = wn + ni * 8 + gid;
                b[ni][0] = Bb[(ks + tid4) * LDB + c];
                b[ni][1] = Bb[(ks + tid4 + 4) * LDB + c];
            }
#pragma unroll
            for (int mi = 0; mi < MI; mi++)
#pragma unroll
                for (int ni = 0; ni < NI; ni++) mma8(acc[mi][ni], a[mi], b[ni]);
        }
        if (k0 + 32 < KTOT) {
            __syncthreads();
            stTiles(cur ^ 1);
            __syncthreads();
        }
    }

    // epilogue
#pragma unroll
    for (int mi = 0; mi < MI; mi++) {
#pragma unroll
        for (int ni = 0; ni < NI; ni++) {
            int r0 = rowBase + wm + mi * 16 + gid;
            int c = wn + ni * 8 + 2 * tid4;
            float2 v0 = make_float2(acc[mi][ni][0], acc[mi][ni][1]);
            float2 v1 = make_float2(acc[mi][ni][2], acc[mi][ni][3]);
            if (RELU) {
                float bx = bias[c], by = bias[c + 1];
                v0.x = fmaxf(v0.x + bx, 0.f); v0.y = fmaxf(v0.y + by, 0.f);
                v1.x = fmaxf(v1.x + bx, 0.f); v1.y = fmaxf(v1.y + by, 0.f);
            }
            if (r0 < NN) *(float2*)&C[(size_t)r0 * ldc + c] = v0;
            if (r0 + 8 < NN) *(float2*)&C[(size_t)(r0 + 8) * ldc + c] = v1;
        }
    }
}

// ---------------- aggregations ----------------
// agg[i] = invdeg[i] * sum_{j in N(i)} feat[j]   (feat stride 128 floats)
__global__ void k_agg0(const float* __restrict__ feat, float* __restrict__ agg) {
    int node = (blockIdx.x * blockDim.x + threadIdx.x) >> 5;
    if (node >= NN) return;
    int lane = threadIdx.x & 31;
    int s = g_off[node], d = g_deg[node];
    const float4* F4 = (const float4*)feat;  // row stride = 32 float4
    float4 acc = make_float4(0.f, 0.f, 0.f, 0.f);
    int k = 0;
    for (; k + 1 < d; k += 2) {
        int j0 = g_csrc[s + k], j1 = g_csrc[s + k + 1];
        float4 v0 = F4[(size_t)j0 * 32 + lane];
        float4 v1 = F4[(size_t)j1 * 32 + lane];
        acc.x += v0.x + v1.x; acc.y += v0.y + v1.y;
        acc.z += v0.z + v1.z; acc.w += v0.w + v1.w;
    }
    if (k < d) {
        int j = g_csrc[s + k];
        float4 v = F4[(size_t)j * 32 + lane];
        acc.x += v.x; acc.y += v.y; acc.z += v.z; acc.w += v.w;
    }
    float sc = g_invdeg[node];
    acc.x *= sc; acc.y *= sc; acc.z *= sc; acc.w *= sc;
    ((float4*)agg)[(size_t)node * 32 + lane] = acc;
}

// out = invdeg * sum_nbr Q[:, 0:32] + b2 + Q[:, 32:64]; Q stride 64
__global__ void k_agg2(const float* __restrict__ Q, const float* __restrict__ b2,
                       float* __restrict__ out) {
    int node = (blockIdx.x * blockDim.x + threadIdx.x) >> 5;
    if (node >= NN) return;
    int lane = threadIdx.x & 31;
    int s = g_off[node], d = g_deg[node];
    float acc = 0.f;
    int k = 0;
    for (; k + 1 < d; k += 2) {
        int j0 = g_csrc[s + k], j1 = g_csrc[s + k + 1];
        acc += Q[(size_t)j0 * 64 + lane] + Q[(size_t)j1 * 64 + lane];
    }
    if (k < d) acc += Q[(size_t)g_csrc[s + k] * 64 + lane];
    out[(size_t)node * 32 + lane] =
        acc * g_invdeg[node] + b2[lane] + Q[(size_t)node * 64 + 32 + lane];
}

extern "C" void kernel_launch(void* const* d_in, const int* in_sizes, int n_in,
                              void* d_out, int out_size) {
    const float* x   = (const float*)d_in[0];
    const void*  ei  = d_in[1];
    const float* W1l = (const float*)d_in[2];
    const float* b1  = (const float*)d_in[3];
    const float* W1r = (const float*)d_in[4];
    const float* W2l = (const float*)d_in[5];
    const float* b2  = (const float*)d_in[6];
    const float* W2r = (const float*)d_in[7];
    float* out = (float*)d_out;

    float *agg = nullptr, *h = nullptr, *Q = nullptr;
    cudaGetSymbolAddress((void**)&agg, g_agg);
    cudaGetSymbolAddress((void**)&h, g_h);
    cudaGetSymbolAddress((void**)&Q, g_Q);

    // dynamic smem: double-buffered As + Bs
    const int smem1 = 2 * (128 * 36 + 32 * (128 + 8)) * (int)sizeof(unsigned);  // 71680
    const int smem2 = 2 * (128 * 36 + 32 * (64 + 8)) * (int)sizeof(unsigned);   // 55296
    cudaFuncSetAttribute(k_mma<128, 4, 256, true, true>,
                         cudaFuncAttributeMaxDynamicSharedMemorySize, smem1);
    cudaFuncSetAttribute(k_mma<64, 2, 128, false, false>,
                         cudaFuncAttributeMaxDynamicSharedMemorySize, smem2);

    // CSR build
    k_init<<<(NN + 255) / 256, 256>>>(ei);
    k_count<<<(EE / 2 + 255) / 256, 256>>>(ei);
    k_scan<<<NB_CHUNK, 256>>>();
    k_fill<<<(EE / 2 + 255) / 256, 256>>>(ei);

    const int MBLK = (NN + 127) / 128;  // 782

    // Layer 1: agg = mean_nbr(x); h = relu([agg | x] @ [W1l; W1r] + b1)
    k_agg0<<<(NN + 7) / 8, 256>>>(x, agg);
    k_mma<128, 4, 256, true, true><<<MBLK, 256, smem1>>>(agg, x, W1l, W1r, b1, h, 128);

    // Layer 2: Q = h @ [W2l | W2r]; out = invdeg*agg(Q_l) + b2 + Q_r
    k_mma<64, 2, 128, false, false><<<MBLK, 256, smem2>>>(h, nullptr, W2l, W2r, nullptr, Q, 64);
    k_agg2<<<(NN + 7) / 8, 256>>>(Q, b2, out);
}